// round 13
// baseline (speedup 1.0000x reference)
#include <cuda_runtime.h>
#include <cuda_fp16.h>
#include <math.h>
#include <stdint.h>

// Problem constants
#define BB   2
#define SS   2048
#define DD   1024
#define HH   16
#define DHH  64

// Scratch (device globals; no allocation allowed)
__device__ __half g_Q  [BB*HH*SS*DHH];  // [B,H,S,DH], fp16, pre-scaled by 0.125
__device__ __half g_K  [BB*HH*SS*DHH];  // [B,H,S,DH]
__device__ __half g_V  [BB*DD*SS];      // TRANSPOSED: [B, dhn(=h*64+dh), S]
__device__ __half g_ctx[BB*SS*DD];      // [B,S,D]
__device__ __half g_xt [BB*SS*DD];
__device__ __half g_yt [BB*SS*DD];
__device__ __half g_Wqt[DD*DD];
__device__ __half g_Wkt[DD*DD];
__device__ __half g_Wvt[DD*DD];
__device__ __half g_Wot[DD*DD];
__device__ uint2  g_mb [BB*SS*(SS/64)]; // bitmask: [b][row][kv-tile64] {even,odd}

// ---------------------------------------------------------------------------
// Helpers
// ---------------------------------------------------------------------------
__device__ __forceinline__ void mma_f16(float d[4], const uint32_t a[4],
                                        uint32_t b0, uint32_t b1) {
    asm volatile(
        "mma.sync.aligned.m16n8k16.row.col.f32.f16.f16.f32 "
        "{%0,%1,%2,%3}, {%4,%5,%6,%7}, {%8,%9}, {%0,%1,%2,%3};"
        : "+f"(d[0]), "+f"(d[1]), "+f"(d[2]), "+f"(d[3])
        : "r"(a[0]), "r"(a[1]), "r"(a[2]), "r"(a[3]), "r"(b0), "r"(b1));
}

__device__ __forceinline__ void ldsm4(uint32_t& r0, uint32_t& r1,
                                      uint32_t& r2, uint32_t& r3,
                                      const __half* p) {
    uint32_t addr = (uint32_t)__cvta_generic_to_shared(p);
    asm volatile("ldmatrix.sync.aligned.m8n8.x4.shared.b16 {%0,%1,%2,%3}, [%4];"
                 : "=r"(r0), "=r"(r1), "=r"(r2), "=r"(r3) : "r"(addr));
}

__device__ __forceinline__ void cp16(void* smem_dst, const void* gsrc) {
    uint32_t s = (uint32_t)__cvta_generic_to_shared(smem_dst);
    asm volatile("cp.async.cg.shared.global [%0], [%1], 16;"
                 :: "r"(s), "l"(gsrc));
}
#define CP_COMMIT() asm volatile("cp.async.commit_group;")
#define CP_WAIT(n)  asm volatile("cp.async.wait_group %0;" :: "n"(n))

__device__ __forceinline__ uint32_t h2u(__half2 h) {
    return *(uint32_t*)&h;
}

// ---------------------------------------------------------------------------
// Pre-pass: fp32 -> fp16 (RN) for 6 tensors (cvt only; mask pack moved into
// the QKV GEMM launch where its DRAM traffic overlaps compute).
// ---------------------------------------------------------------------------
struct PreArgs {
    const float* src[6];
    __half*      dst[6];
    int          n4[6];
};

__global__ void prepass_kernel(PreArgs args) {
    const int slot = blockIdx.y;
    const float* __restrict__ src = args.src[slot];
    __half* __restrict__ dst = args.dst[slot];
    const int n4 = args.n4[slot];
    for (int i = blockIdx.x * blockDim.x + threadIdx.x; i < n4;
         i += gridDim.x * blockDim.x) {
        float4 v = ((const float4*)src)[i];
        __half2 h0 = __floats2half2_rn(v.x, v.y);
        __half2 h1 = __floats2half2_rn(v.z, v.w);
        uint2 u; u.x = h2u(h0); u.y = h2u(h1);
        ((uint2*)dst)[i] = u;
    }
}

// ---------------------------------------------------------------------------
// fp16 GEMM, multi-slice: blockIdx.z selects {A, W, bias, out, scale, mode}.
// CTA 128x128, BK=64, 8 warps (2x4 -> 64x32 warp tile), cp.async dbl buffer.
// mode 0: fp32 out [M][N], m=by, n=bx
// mode 1: half out head-split [B,H,S,DH], scaled; m=by, n=bx
// mode 2: half out transposed [B, m, s], bias by m; m=bx, n=by
// mode 3: MASK BITPACK slice (A = mask ints, out = uint2 bitmask); no GEMM.
// ---------------------------------------------------------------------------
#define GHS  72
#define GTILE (128 * GHS)
#define GEMM_SMEM (4 * GTILE * 2)   // 73728 B

struct GemmSlice {
    const __half* A;
    const __half* W;
    const float*  bias;
    void*         out;
    float         scale;
    int           mode;
};
struct GemmArgs { GemmSlice sl[4]; };

__global__ void __launch_bounds__(256, 2) gemm_f16_multi(GemmArgs args)
{
    extern __shared__ __half smh[];
    const GemmSlice sl = args.sl[blockIdx.z];
    const int mode = sl.mode;

    if (mode == 3) {
        // Mask bitpack: grid-stride over BB*SS*(SS/64) warp-tasks.
        const int* __restrict__ mask = (const int*)sl.A;
        uint2* __restrict__ mb = (uint2*)sl.out;
        const int lane = threadIdx.x & 31;
        const int warps_per_cta = blockDim.x >> 5;
        const int cta = blockIdx.x + gridDim.x * blockIdx.y;   // 0..255
        const int w0 = cta * warps_per_cta + (threadIdx.x >> 5);
        const int warps_total = gridDim.x * gridDim.y * warps_per_cta;
        const int n_tasks = BB * SS * (SS / 64);
        for (int t = w0; t < n_tasks; t += warps_total) {
            const size_t base = (size_t)t * 64;
            int v0 = mask[base + 2 * lane];
            int v1 = mask[base + 2 * lane + 1];
            uint32_t we = __ballot_sync(0xffffffffu, v0 != 0);
            uint32_t wo = __ballot_sync(0xffffffffu, v1 != 0);
            if (lane == 0) mb[t] = make_uint2(we, wo);
        }
        return;
    }

    __half* As = smh;
    __half* Bs = smh + 2 * GTILE;

    const __half* __restrict__ A = sl.A;
    const __half* __restrict__ W = sl.W;
    const float*  __restrict__ bias = sl.bias;

    const int tid  = threadIdx.x;
    const int lane = tid & 31;
    const int wid  = tid >> 5;
    const int wm   = wid >> 2;
    const int wn   = wid & 3;
    const int g    = lane >> 2;
    const int a    = lane & 3;
    const int m0   = (mode == 2 ? blockIdx.x : blockIdx.y) * 128;
    const int n0   = (mode == 2 ? blockIdx.y : blockIdx.x) * 128;

    const int lr15  = lane & 15;
    const int ahalf = (lane >> 4) << 3;
    const int br8   = (lane & 7) + ((lane >> 4) << 3);
    const int bhalf = ((lane >> 3) & 1) << 3;

    float acc[4][4][4];
#pragma unroll
    for (int mi = 0; mi < 4; mi++)
#pragma unroll
        for (int nj = 0; nj < 4; nj++)
#pragma unroll
            for (int c = 0; c < 4; c++) acc[mi][nj][c] = 0.0f;

    auto stage = [&](int buf, int k0) {
#pragma unroll
        for (int i = 0; i < 4; i++) {
            int e = tid + 256 * i;
            int r = e >> 3, c8 = e & 7;
            cp16(&As[buf * GTILE + r * GHS + c8 * 8],
                 &A[(size_t)(m0 + r) * DD + k0 + c8 * 8]);
            cp16(&Bs[buf * GTILE + r * GHS + c8 * 8],
                 &W[(size_t)(n0 + r) * DD + k0 + c8 * 8]);
        }
    };

    stage(0, 0);
    CP_COMMIT();

    for (int s = 0; s < 16; s++) {
        if (s < 15) {
            stage((s + 1) & 1, (s + 1) * 64);
            CP_COMMIT();
            CP_WAIT(1);
        } else {
            CP_WAIT(0);
        }
        __syncthreads();

        const __half* Ab = &As[(s & 1) * GTILE];
        const __half* Bb = &Bs[(s & 1) * GTILE];

#pragma unroll
        for (int ks = 0; ks < 4; ks++) {
            uint32_t af[4][4], bf[4][2];
#pragma unroll
            for (int mi = 0; mi < 4; mi++)
                ldsm4(af[mi][0], af[mi][1], af[mi][2], af[mi][3],
                      &Ab[(wm * 64 + mi * 16 + lr15) * GHS + ks * 16 + ahalf]);
#pragma unroll
            for (int njp = 0; njp < 2; njp++)
                ldsm4(bf[2*njp][0], bf[2*njp][1], bf[2*njp+1][0], bf[2*njp+1][1],
                      &Bb[(wn * 32 + njp * 16 + br8) * GHS + ks * 16 + bhalf]);
#pragma unroll
            for (int mi = 0; mi < 4; mi++)
#pragma unroll
                for (int nj = 0; nj < 4; nj++)
                    mma_f16(acc[mi][nj], af[mi], bf[nj][0], bf[nj][1]);
        }
        __syncthreads();
    }

#pragma unroll
    for (int mi = 0; mi < 4; mi++) {
#pragma unroll
        for (int nj = 0; nj < 4; nj++) {
            int m = m0 + wm * 64 + mi * 16 + g;
            int n = n0 + wn * 32 + nj * 8 + 2 * a;
            if (mode == 2) {
                __half* out = (__half*)sl.out;
                float bm0 = bias[m], bm1 = bias[m + 8];
                int b = n >> 11, sq = n & 2047;
                size_t base = (size_t)b * DD * SS + sq;
                *(__half2*)&out[base + (size_t)m * SS] =
                    __floats2half2_rn(acc[mi][nj][0] + bm0, acc[mi][nj][1] + bm0);
                *(__half2*)&out[base + (size_t)(m + 8) * SS] =
                    __floats2half2_rn(acc[mi][nj][2] + bm1, acc[mi][nj][3] + bm1);
            } else if (mode == 1) {
                __half* out = (__half*)sl.out;
                float2 bv = *(const float2*)&bias[n];
                float scale = sl.scale;
                int h = n >> 6, dh = n & 63;
                int b1_ = m >> 11, s1 = m & 2047;
                *(__half2*)&out[(((size_t)(b1_ * HH + h)) * SS + s1) * DHH + dh] =
                    __floats2half2_rn((acc[mi][nj][0] + bv.x) * scale,
                                      (acc[mi][nj][1] + bv.y) * scale);
                int m2 = m + 8, b2_ = m2 >> 11, s2 = m2 & 2047;
                *(__half2*)&out[(((size_t)(b2_ * HH + h)) * SS + s2) * DHH + dh] =
                    __floats2half2_rn((acc[mi][nj][2] + bv.x) * scale,
                                      (acc[mi][nj][3] + bv.y) * scale);
            } else {
                float* out = (float*)sl.out;
                float2 bv = *(const float2*)&bias[n];
                *(float2*)&out[(size_t)m * DD + n] =
                    make_float2(acc[mi][nj][0] + bv.x, acc[mi][nj][1] + bv.y);
                *(float2*)&out[(size_t)(m + 8) * DD + n] =
                    make_float2(acc[mi][nj][2] + bv.x, acc[mi][nj][3] + bv.y);
            }
        }
    }
}

// ---------------------------------------------------------------------------
// Flash attention, fp16 mma + ldmatrix, S/PV INTERLEAVED (PV k-step nfp
// consumes exactly the P fragments S-block nfp produces -> p lives in 8 regs,
// not 32). CTA 128 thr (4 warps), q-tile 128 (32 rows/warp, mi=2), kv-tile
// 64, three-deep cp.async ring, one __syncthreads per iter. 3 CTAs/SM.
// smem: K[3][64][72] + Vt[3][64][72] halves = 55296 B.
// ---------------------------------------------------------------------------
#define AHS 72
#define AT  (64 * AHS)
#define ATTN_SMEM (6 * AT * 2)   // 55296 B

__global__ void __launch_bounds__(128, 3) attn_f16(
    const __half* __restrict__ Q, const __half* __restrict__ K,
    const __half* __restrict__ Vt, const uint2* __restrict__ mb,
    __half* __restrict__ ctx)
{
    extern __shared__ __half smh[];
    __half* Kr = smh;                 // [3][64][72]  rows=kv, cols=dh
    __half* Vr = smh + 3 * AT;        // [3][64][72]  rows=dh, cols=kv

    const int q0   = blockIdx.x * 128;
    const int h    = blockIdx.y;
    const int b    = blockIdx.z;
    const int tid  = threadIdx.x;
    const int lane = tid & 31;
    const int wid  = tid >> 5;
    const int g    = lane >> 2;
    const int a    = lane & 3;
    const int wr   = wid * 32;
    const int bh   = b * HH + h;

    const int br8   = (lane & 7) + ((lane >> 4) << 3);
    const int bhalf = ((lane >> 3) & 1) << 3;

    const __half* Qp  = Q  + ((size_t)bh * SS + q0) * DHH;
    const __half* Kp  = K  + (size_t)bh * SS * DHH;
    const __half* Vtp = Vt + ((size_t)b * DD + h * DHH) * SS;
    const uint2*  Mb  = mb + ((size_t)b * SS + q0) * (SS / 64);

    uint32_t aq[2][4][4];
#pragma unroll
    for (int mi = 0; mi < 2; mi++) {
        int r = wr + mi * 16 + g;
#pragma unroll
        for (int ks = 0; ks < 4; ks++) {
            aq[mi][ks][0] = *(const uint32_t*)&Qp[(r)     * DHH + ks*16 + 2*a];
            aq[mi][ks][1] = *(const uint32_t*)&Qp[(r + 8) * DHH + ks*16 + 2*a];
            aq[mi][ks][2] = *(const uint32_t*)&Qp[(r)     * DHH + ks*16 + 2*a + 8];
            aq[mi][ks][3] = *(const uint32_t*)&Qp[(r + 8) * DHH + ks*16 + 2*a + 8];
        }
    }

    float o[2][8][4];
#pragma unroll
    for (int mi = 0; mi < 2; mi++)
#pragma unroll
        for (int nf = 0; nf < 8; nf++)
#pragma unroll
            for (int c = 0; c < 4; c++) o[mi][nf][c] = 0.0f;
    float lr[2][2] = {{0.0f, 0.0f}, {0.0f, 0.0f}};

    auto stageKV = [&](int buf, int kv0) {
#pragma unroll
        for (int i = 0; i < 4; i++) {
            int e = tid + 128 * i;
            int r = e >> 3, c8 = e & 7;
            cp16(&Kr[buf * AT + r * AHS + c8 * 8],
                 &Kp[(size_t)(kv0 + r) * DHH + c8 * 8]);
            cp16(&Vr[buf * AT + r * AHS + c8 * 8],
                 &Vtp[(size_t)r * SS + kv0 + c8 * 8]);
        }
    };

    stageKV(0, 0);   CP_COMMIT();
    stageKV(1, 64);  CP_COMMIT();

    for (int it = 0; it < 32; it++) {
        const int kv0 = it * 64;
        const int buf = it % 3;
        if (it == 31) { CP_WAIT(0); } else { CP_WAIT(1); }
        __syncthreads();
        if (it + 2 < 32) {
            stageKV((it + 2) % 3, kv0 + 128);
            CP_COMMIT();
        }

        const __half* Kb = &Kr[buf * AT];
        const __half* Vb = &Vr[buf * AT];

        uint2 W00 = Mb[(size_t)(wr + g)      * (SS/64) + it];
        uint2 W01 = Mb[(size_t)(wr + 8 + g)  * (SS/64) + it];
        uint2 W10 = Mb[(size_t)(wr + 16 + g) * (SS/64) + it];
        uint2 W11 = Mb[(size_t)(wr + 24 + g) * (SS/64) + it];

        // Interleaved: S-block nfp -> exp/pack -> PV k-step kf = nfp
#pragma unroll
        for (int nfp = 0; nfp < 4; nfp++) {
            float s00[4] = {0,0,0,0}, s01[4] = {0,0,0,0};
            float s10[4] = {0,0,0,0}, s11[4] = {0,0,0,0};
#pragma unroll
            for (int ks = 0; ks < 4; ks++) {
                uint32_t b0a, b1a, b0b, b1b;
                ldsm4(b0a, b1a, b0b, b1b,
                      &Kb[(nfp * 16 + br8) * AHS + ks * 16 + bhalf]);
                mma_f16(s00, aq[0][ks], b0a, b1a);
                mma_f16(s01, aq[0][ks], b0b, b1b);
                mma_f16(s10, aq[1][ks], b0a, b1a);
                mma_f16(s11, aq[1][ks], b0b, b1b);
            }

            uint32_t ap0[4], ap1[4];
#pragma unroll
            for (int half_ = 0; half_ < 2; half_++) {
                int nf = nfp * 2 + half_;
                int bit = nf * 4 + a;
                const float* sv0 = half_ ? s01 : s00;
                const float* sv1 = half_ ? s11 : s10;
                {
                    float e0 = __expf(sv0[0]); e0 = (W00.x >> bit) & 1 ? e0 : 0.0f;
                    float e1 = __expf(sv0[1]); e1 = (W00.y >> bit) & 1 ? e1 : 0.0f;
                    float e2 = __expf(sv0[2]); e2 = (W01.x >> bit) & 1 ? e2 : 0.0f;
                    float e3 = __expf(sv0[3]); e3 = (W01.y >> bit) & 1 ? e3 : 0.0f;
                    lr[0][0] += e0 + e1;
                    lr[0][1] += e2 + e3;
                    ap0[2*half_]     = h2u(__floats2half2_rn(e0, e1));
                    ap0[2*half_ + 1] = h2u(__floats2half2_rn(e2, e3));
                }
                {
                    float e0 = __expf(sv1[0]); e0 = (W10.x >> bit) & 1 ? e0 : 0.0f;
                    float e1 = __expf(sv1[1]); e1 = (W10.y >> bit) & 1 ? e1 : 0.0f;
                    float e2 = __expf(sv1[2]); e2 = (W11.x >> bit) & 1 ? e2 : 0.0f;
                    float e3 = __expf(sv1[3]); e3 = (W11.y >> bit) & 1 ? e3 : 0.0f;
                    lr[1][0] += e0 + e1;
                    lr[1][1] += e2 + e3;
                    ap1[2*half_]     = h2u(__floats2half2_rn(e0, e1));
                    ap1[2*half_ + 1] = h2u(__floats2half2_rn(e2, e3));
                }
            }

            // PV k-step kf = nfp (A-operand layout: {nf0_r0, nf0_r8, nf1_r0, nf1_r8})
#pragma unroll
            for (int vf = 0; vf < 4; vf++) {
                uint32_t b0a, b1a, b0b, b1b;
                ldsm4(b0a, b1a, b0b, b1b,
                      &Vb[(vf * 16 + br8) * AHS + nfp * 16 + bhalf]);
                mma_f16(o[0][2*vf],     ap0, b0a, b1a);
                mma_f16(o[0][2*vf + 1], ap0, b0b, b1b);
                mma_f16(o[1][2*vf],     ap1, b0a, b1a);
                mma_f16(o[1][2*vf + 1], ap1, b0b, b1b);
            }
        }
    }

#pragma unroll
    for (int mi = 0; mi < 2; mi++) {
        lr[mi][0] += __shfl_xor_sync(0xffffffffu, lr[mi][0], 1);
        lr[mi][0] += __shfl_xor_sync(0xffffffffu, lr[mi][0], 2);
        lr[mi][1] += __shfl_xor_sync(0xffffffffu, lr[mi][1], 1);
        lr[mi][1] += __shfl_xor_sync(0xffffffffu, lr[mi][1], 2);
    }

#pragma unroll
    for (int mi = 0; mi < 2; mi++) {
        int rlo = wr + mi * 16 + g;
        float inv0 = 1.0f / lr[mi][0];
        float inv1 = 1.0f / lr[mi][1];
#pragma unroll
        for (int nf = 0; nf < 8; nf++) {
            int dh = h * DHH + nf*8 + 2*a;
            *(__half2*)&ctx[((size_t)(b * SS) + q0 + rlo) * DD + dh] =
                __floats2half2_rn(o[mi][nf][0] * inv0, o[mi][nf][1] * inv0);
            *(__half2*)&ctx[((size_t)(b * SS) + q0 + rlo + 8) * DD + dh] =
                __floats2half2_rn(o[mi][nf][2] * inv1, o[mi][nf][3] * inv1);
        }
    }
}

// ---------------------------------------------------------------------------
// Launch
// ---------------------------------------------------------------------------
extern "C" void kernel_launch(void* const* d_in, const int* in_sizes, int n_in,
                              void* d_out, int out_size)
{
    const float* x   = (const float*)d_in[0];
    const float* y   = (const float*)d_in[1];
    const int*   msk = (const int*)  d_in[2];
    const float* Wq  = (const float*)d_in[3];
    const float* bq  = (const float*)d_in[4];
    const float* Wk  = (const float*)d_in[5];
    const float* bk  = (const float*)d_in[6];
    const float* Wv  = (const float*)d_in[7];
    const float* bv  = (const float*)d_in[8];
    const float* Wo  = (const float*)d_in[9];
    const float* bo  = (const float*)d_in[10];
    float* out = (float*)d_out;

    __half *Qg, *Kg, *Vg, *Cg, *xt, *yt, *wqt, *wkt, *wvt, *wot;
    uint2* mbg;
    cudaGetSymbolAddress((void**)&Qg,  g_Q);
    cudaGetSymbolAddress((void**)&Kg,  g_K);
    cudaGetSymbolAddress((void**)&Vg,  g_V);
    cudaGetSymbolAddress((void**)&Cg,  g_ctx);
    cudaGetSymbolAddress((void**)&xt,  g_xt);
    cudaGetSymbolAddress((void**)&yt,  g_yt);
    cudaGetSymbolAddress((void**)&wqt, g_Wqt);
    cudaGetSymbolAddress((void**)&wkt, g_Wkt);
    cudaGetSymbolAddress((void**)&wvt, g_Wvt);
    cudaGetSymbolAddress((void**)&wot, g_Wot);
    cudaGetSymbolAddress((void**)&mbg, g_mb);

    cudaFuncSetAttribute(gemm_f16_multi,
        cudaFuncAttributeMaxDynamicSharedMemorySize, GEMM_SMEM);
    cudaFuncSetAttribute(attn_f16,
        cudaFuncAttributeMaxDynamicSharedMemorySize, ATTN_SMEM);

    // Pre-pass: 6 cvt slots only (mask pack rides with the QKV launch)
    const int NX = BB * SS * DD / 4;
    const int NW = DD * DD / 4;
    PreArgs pa;
    pa.src[0] = x;  pa.dst[0] = xt;  pa.n4[0] = NX;
    pa.src[1] = y;  pa.dst[1] = yt;  pa.n4[1] = NX;
    pa.src[2] = Wq; pa.dst[2] = wqt; pa.n4[2] = NW;
    pa.src[3] = Wk; pa.dst[3] = wkt; pa.n4[3] = NW;
    pa.src[4] = Wv; pa.dst[4] = wvt; pa.n4[4] = NW;
    pa.src[5] = Wo; pa.dst[5] = wot; pa.n4[5] = NW;
    prepass_kernel<<<dim3(1024, 6), 256>>>(pa);

    // Fused Q + K + V^T projections + mask bitpack: one launch, 1024 CTAs
    GemmArgs ga;
    ga.sl[0] = {xt,  wqt, bq, (void*)Qg, 0.125f, 1};
    ga.sl[1] = {yt,  wkt, bk, (void*)Kg, 1.0f,   1};
    ga.sl[2] = {wvt, yt,  bv, (void*)Vg, 1.0f,   2};
    ga.sl[3] = {(const __half*)msk, nullptr, nullptr, (void*)mbg, 0.0f, 3};
    gemm_f16_multi<<<dim3(8, 32, 4), 256, GEMM_SMEM>>>(ga);

    attn_f16<<<dim3(SS / 128, HH, BB), 128, ATTN_SMEM>>>(Qg, Kg, Vg, mbg, Cg);

    // Output projection (single slice, mode 0)
    GemmArgs go;
    go.sl[0] = {Cg, wot, bo, (void*)out, 1.0f, 0};
    go.sl[1] = go.sl[0];
    go.sl[2] = go.sl[0];
    go.sl[3] = go.sl[0];
    gemm_f16_multi<<<dim3(8, 32, 1), 256, GEMM_SMEM>>>(go);
}

// round 14
// speedup vs baseline: 1.0095x; 1.0095x over previous
#include <cuda_runtime.h>
#include <cuda_fp16.h>
#include <math.h>
#include <stdint.h>

// Problem constants
#define BB   2
#define SS   2048
#define DD   1024
#define HH   16
#define DHH  64

// Scratch (device globals; no allocation allowed)
__device__ __half g_Q  [BB*HH*SS*DHH];  // [B,H,S,DH], fp16, pre-scaled by 0.125
__device__ __half g_K  [BB*HH*SS*DHH];  // [B,H,S,DH]
__device__ __half g_V  [BB*DD*SS];      // TRANSPOSED: [B, dhn(=h*64+dh), S]
__device__ __half g_ctx[BB*SS*DD];      // [B,S,D]
__device__ __half g_xt [BB*SS*DD];
__device__ __half g_yt [BB*SS*DD];
__device__ __half g_Wqt[DD*DD];
__device__ __half g_Wkt[DD*DD];
__device__ __half g_Wvt[DD*DD];
__device__ __half g_Wot[DD*DD];
__device__ uint2  g_mb [BB*SS*(SS/64)]; // bitmask: [b][row][kv-tile64] {even,odd}

// ---------------------------------------------------------------------------
// Helpers
// ---------------------------------------------------------------------------
__device__ __forceinline__ void mma_f16(float d[4], const uint32_t a[4],
                                        uint32_t b0, uint32_t b1) {
    asm volatile(
        "mma.sync.aligned.m16n8k16.row.col.f32.f16.f16.f32 "
        "{%0,%1,%2,%3}, {%4,%5,%6,%7}, {%8,%9}, {%0,%1,%2,%3};"
        : "+f"(d[0]), "+f"(d[1]), "+f"(d[2]), "+f"(d[3])
        : "r"(a[0]), "r"(a[1]), "r"(a[2]), "r"(a[3]), "r"(b0), "r"(b1));
}

__device__ __forceinline__ void ldsm4(uint32_t& r0, uint32_t& r1,
                                      uint32_t& r2, uint32_t& r3,
                                      const __half* p) {
    uint32_t addr = (uint32_t)__cvta_generic_to_shared(p);
    asm volatile("ldmatrix.sync.aligned.m8n8.x4.shared.b16 {%0,%1,%2,%3}, [%4];"
                 : "=r"(r0), "=r"(r1), "=r"(r2), "=r"(r3) : "r"(addr));
}

__device__ __forceinline__ void cp16(void* smem_dst, const void* gsrc) {
    uint32_t s = (uint32_t)__cvta_generic_to_shared(smem_dst);
    asm volatile("cp.async.cg.shared.global [%0], [%1], 16;"
                 :: "r"(s), "l"(gsrc));
}
#define CP_COMMIT() asm volatile("cp.async.commit_group;")
#define CP_WAIT(n)  asm volatile("cp.async.wait_group %0;" :: "n"(n))

__device__ __forceinline__ uint32_t h2u(__half2 h) {
    return *(uint32_t*)&h;
}

// ---------------------------------------------------------------------------
// Pre-pass: fp32 -> fp16 (RN) for 6 tensors (cvt only).
// ---------------------------------------------------------------------------
struct PreArgs {
    const float* src[6];
    __half*      dst[6];
    int          n4[6];
};

__global__ void prepass_kernel(PreArgs args) {
    const int slot = blockIdx.y;
    const float* __restrict__ src = args.src[slot];
    __half* __restrict__ dst = args.dst[slot];
    const int n4 = args.n4[slot];
    for (int i = blockIdx.x * blockDim.x + threadIdx.x; i < n4;
         i += gridDim.x * blockDim.x) {
        float4 v = ((const float4*)src)[i];
        __half2 h0 = __floats2half2_rn(v.x, v.y);
        __half2 h1 = __floats2half2_rn(v.z, v.w);
        uint2 u; u.x = h2u(h0); u.y = h2u(h1);
        ((uint2*)dst)[i] = u;
    }
}

// ---------------------------------------------------------------------------
// Mask bitpack (runs on a second stream, overlapping cvt + QKV GEMM).
// word.x bit i = mask[col 2i] != 0 ; word.y bit i = mask[col 2i+1] != 0.
// ---------------------------------------------------------------------------
__global__ void mask_pack_kernel(const int* __restrict__ mask,
                                 uint2* __restrict__ mb) {
    const int lane = threadIdx.x & 31;
    const int warps_total = (gridDim.x * blockDim.x) >> 5;
    const int w0 = (blockIdx.x * blockDim.x + threadIdx.x) >> 5;
    const int n_tasks = BB * SS * (SS / 64);
    for (int t = w0; t < n_tasks; t += warps_total) {
        const size_t base = (size_t)t * 64;
        int v0 = mask[base + 2 * lane];
        int v1 = mask[base + 2 * lane + 1];
        uint32_t we = __ballot_sync(0xffffffffu, v0 != 0);
        uint32_t wo = __ballot_sync(0xffffffffu, v1 != 0);
        if (lane == 0) mb[t] = make_uint2(we, wo);
    }
}

// ---------------------------------------------------------------------------
// fp16 GEMM, multi-slice (R12 form): blockIdx.z selects the slice.
// CTA 128x128, BK=64, 8 warps (2x4 -> 64x32 warp tile), cp.async dbl buffer.
// mode 0: fp32 out [M][N], m=by, n=bx
// mode 1: half out head-split [B,H,S,DH], scaled; m=by, n=bx
// mode 2: half out transposed [B, m, s], bias by m; m=bx, n=by
// ---------------------------------------------------------------------------
#define GHS  72
#define GTILE (128 * GHS)
#define GEMM_SMEM (4 * GTILE * 2)   // 73728 B

struct GemmSlice {
    const __half* A;
    const __half* W;
    const float*  bias;
    void*         out;
    float         scale;
    int           mode;
};
struct GemmArgs { GemmSlice sl[3]; };

__global__ void __launch_bounds__(256, 2) gemm_f16_multi(GemmArgs args)
{
    extern __shared__ __half smh[];
    __half* As = smh;
    __half* Bs = smh + 2 * GTILE;

    const GemmSlice sl = args.sl[blockIdx.z];
    const int mode = sl.mode;
    const __half* __restrict__ A = sl.A;
    const __half* __restrict__ W = sl.W;
    const float*  __restrict__ bias = sl.bias;

    const int tid  = threadIdx.x;
    const int lane = tid & 31;
    const int wid  = tid >> 5;
    const int wm   = wid >> 2;
    const int wn   = wid & 3;
    const int g    = lane >> 2;
    const int a    = lane & 3;
    const int m0   = (mode == 2 ? blockIdx.x : blockIdx.y) * 128;
    const int n0   = (mode == 2 ? blockIdx.y : blockIdx.x) * 128;

    const int lr15  = lane & 15;
    const int ahalf = (lane >> 4) << 3;
    const int br8   = (lane & 7) + ((lane >> 4) << 3);
    const int bhalf = ((lane >> 3) & 1) << 3;

    float acc[4][4][4];
#pragma unroll
    for (int mi = 0; mi < 4; mi++)
#pragma unroll
        for (int nj = 0; nj < 4; nj++)
#pragma unroll
            for (int c = 0; c < 4; c++) acc[mi][nj][c] = 0.0f;

    auto stage = [&](int buf, int k0) {
#pragma unroll
        for (int i = 0; i < 4; i++) {
            int e = tid + 256 * i;
            int r = e >> 3, c8 = e & 7;
            cp16(&As[buf * GTILE + r * GHS + c8 * 8],
                 &A[(size_t)(m0 + r) * DD + k0 + c8 * 8]);
            cp16(&Bs[buf * GTILE + r * GHS + c8 * 8],
                 &W[(size_t)(n0 + r) * DD + k0 + c8 * 8]);
        }
    };

    stage(0, 0);
    CP_COMMIT();

    for (int s = 0; s < 16; s++) {
        if (s < 15) {
            stage((s + 1) & 1, (s + 1) * 64);
            CP_COMMIT();
            CP_WAIT(1);
        } else {
            CP_WAIT(0);
        }
        __syncthreads();

        const __half* Ab = &As[(s & 1) * GTILE];
        const __half* Bb = &Bs[(s & 1) * GTILE];

#pragma unroll
        for (int ks = 0; ks < 4; ks++) {
            uint32_t af[4][4], bf[4][2];
#pragma unroll
            for (int mi = 0; mi < 4; mi++)
                ldsm4(af[mi][0], af[mi][1], af[mi][2], af[mi][3],
                      &Ab[(wm * 64 + mi * 16 + lr15) * GHS + ks * 16 + ahalf]);
#pragma unroll
            for (int njp = 0; njp < 2; njp++)
                ldsm4(bf[2*njp][0], bf[2*njp][1], bf[2*njp+1][0], bf[2*njp+1][1],
                      &Bb[(wn * 32 + njp * 16 + br8) * GHS + ks * 16 + bhalf]);
#pragma unroll
            for (int mi = 0; mi < 4; mi++)
#pragma unroll
                for (int nj = 0; nj < 4; nj++)
                    mma_f16(acc[mi][nj], af[mi], bf[nj][0], bf[nj][1]);
        }
        __syncthreads();
    }

#pragma unroll
    for (int mi = 0; mi < 4; mi++) {
#pragma unroll
        for (int nj = 0; nj < 4; nj++) {
            int m = m0 + wm * 64 + mi * 16 + g;
            int n = n0 + wn * 32 + nj * 8 + 2 * a;
            if (mode == 2) {
                __half* out = (__half*)sl.out;
                float bm0 = bias[m], bm1 = bias[m + 8];
                int b = n >> 11, sq = n & 2047;
                size_t base = (size_t)b * DD * SS + sq;
                *(__half2*)&out[base + (size_t)m * SS] =
                    __floats2half2_rn(acc[mi][nj][0] + bm0, acc[mi][nj][1] + bm0);
                *(__half2*)&out[base + (size_t)(m + 8) * SS] =
                    __floats2half2_rn(acc[mi][nj][2] + bm1, acc[mi][nj][3] + bm1);
            } else if (mode == 1) {
                __half* out = (__half*)sl.out;
                float2 bv = *(const float2*)&bias[n];
                float scale = sl.scale;
                int h = n >> 6, dh = n & 63;
                int b1_ = m >> 11, s1 = m & 2047;
                *(__half2*)&out[(((size_t)(b1_ * HH + h)) * SS + s1) * DHH + dh] =
                    __floats2half2_rn((acc[mi][nj][0] + bv.x) * scale,
                                      (acc[mi][nj][1] + bv.y) * scale);
                int m2 = m + 8, b2_ = m2 >> 11, s2 = m2 & 2047;
                *(__half2*)&out[(((size_t)(b2_ * HH + h)) * SS + s2) * DHH + dh] =
                    __floats2half2_rn((acc[mi][nj][2] + bv.x) * scale,
                                      (acc[mi][nj][3] + bv.y) * scale);
            } else {
                float* out = (float*)sl.out;
                float2 bv = *(const float2*)&bias[n];
                *(float2*)&out[(size_t)m * DD + n] =
                    make_float2(acc[mi][nj][0] + bv.x, acc[mi][nj][1] + bv.y);
                *(float2*)&out[(size_t)(m + 8) * DD + n] =
                    make_float2(acc[mi][nj][2] + bv.x, acc[mi][nj][3] + bv.y);
            }
        }
    }
}

// ---------------------------------------------------------------------------
// Flash attention (R12 form): fp16 mma + ldmatrix, separate S and PV phases
// (P in registers), q-tile 128 (32 rows/warp, mi=2), kv-tile 64, three-deep
// cp.async ring, one __syncthreads per iter.
// smem: K[3][64][72] + Vt[3][64][72] halves = 55296 B.
// ---------------------------------------------------------------------------
#define AHS 72
#define AT  (64 * AHS)
#define ATTN_SMEM (6 * AT * 2)   // 55296 B

__global__ void __launch_bounds__(128) attn_f16(
    const __half* __restrict__ Q, const __half* __restrict__ K,
    const __half* __restrict__ Vt, const uint2* __restrict__ mb,
    __half* __restrict__ ctx)
{
    extern __shared__ __half smh[];
    __half* Kr = smh;                 // [3][64][72]  rows=kv, cols=dh
    __half* Vr = smh + 3 * AT;        // [3][64][72]  rows=dh, cols=kv

    const int q0   = blockIdx.x * 128;
    const int h    = blockIdx.y;
    const int b    = blockIdx.z;
    const int tid  = threadIdx.x;
    const int lane = tid & 31;
    const int wid  = tid >> 5;
    const int g    = lane >> 2;
    const int a    = lane & 3;
    const int wr   = wid * 32;
    const int bh   = b * HH + h;

    const int br8   = (lane & 7) + ((lane >> 4) << 3);
    const int bhalf = ((lane >> 3) & 1) << 3;

    const __half* Qp  = Q  + ((size_t)bh * SS + q0) * DHH;
    const __half* Kp  = K  + (size_t)bh * SS * DHH;
    const __half* Vtp = Vt + ((size_t)b * DD + h * DHH) * SS;
    const uint2*  Mb  = mb + ((size_t)b * SS + q0) * (SS / 64);

    uint32_t aq[2][4][4];
#pragma unroll
    for (int mi = 0; mi < 2; mi++) {
        int r = wr + mi * 16 + g;
#pragma unroll
        for (int ks = 0; ks < 4; ks++) {
            aq[mi][ks][0] = *(const uint32_t*)&Qp[(r)     * DHH + ks*16 + 2*a];
            aq[mi][ks][1] = *(const uint32_t*)&Qp[(r + 8) * DHH + ks*16 + 2*a];
            aq[mi][ks][2] = *(const uint32_t*)&Qp[(r)     * DHH + ks*16 + 2*a + 8];
            aq[mi][ks][3] = *(const uint32_t*)&Qp[(r + 8) * DHH + ks*16 + 2*a + 8];
        }
    }

    float o[2][8][4];
#pragma unroll
    for (int mi = 0; mi < 2; mi++)
#pragma unroll
        for (int nf = 0; nf < 8; nf++)
#pragma unroll
            for (int c = 0; c < 4; c++) o[mi][nf][c] = 0.0f;
    float lr[2][2] = {{0.0f, 0.0f}, {0.0f, 0.0f}};

    auto stageKV = [&](int buf, int kv0) {
#pragma unroll
        for (int i = 0; i < 4; i++) {
            int e = tid + 128 * i;
            int r = e >> 3, c8 = e & 7;
            cp16(&Kr[buf * AT + r * AHS + c8 * 8],
                 &Kp[(size_t)(kv0 + r) * DHH + c8 * 8]);
            cp16(&Vr[buf * AT + r * AHS + c8 * 8],
                 &Vtp[(size_t)r * SS + kv0 + c8 * 8]);
        }
    };

    stageKV(0, 0);   CP_COMMIT();
    stageKV(1, 64);  CP_COMMIT();

    for (int it = 0; it < 32; it++) {
        const int kv0 = it * 64;
        const int buf = it % 3;
        if (it == 31) { CP_WAIT(0); } else { CP_WAIT(1); }
        __syncthreads();
        if (it + 2 < 32) {
            stageKV((it + 2) % 3, kv0 + 128);
            CP_COMMIT();
        }

        const __half* Kb = &Kr[buf * AT];
        const __half* Vb = &Vr[buf * AT];

        uint2 W00 = Mb[(size_t)(wr + g)      * (SS/64) + it];
        uint2 W01 = Mb[(size_t)(wr + 8 + g)  * (SS/64) + it];
        uint2 W10 = Mb[(size_t)(wr + 16 + g) * (SS/64) + it];
        uint2 W11 = Mb[(size_t)(wr + 24 + g) * (SS/64) + it];

        uint32_t p[2][8][2];
#pragma unroll
        for (int nfp = 0; nfp < 4; nfp++) {
            float s00[4] = {0,0,0,0}, s01[4] = {0,0,0,0};
            float s10[4] = {0,0,0,0}, s11[4] = {0,0,0,0};
#pragma unroll
            for (int ks = 0; ks < 4; ks++) {
                uint32_t b0a, b1a, b0b, b1b;
                ldsm4(b0a, b1a, b0b, b1b,
                      &Kb[(nfp * 16 + br8) * AHS + ks * 16 + bhalf]);
                mma_f16(s00, aq[0][ks], b0a, b1a);
                mma_f16(s01, aq[0][ks], b0b, b1b);
                mma_f16(s10, aq[1][ks], b0a, b1a);
                mma_f16(s11, aq[1][ks], b0b, b1b);
            }
#pragma unroll
            for (int half_ = 0; half_ < 2; half_++) {
                int nf = nfp * 2 + half_;
                int bit = nf * 4 + a;
                const float* sv0 = half_ ? s01 : s00;
                const float* sv1 = half_ ? s11 : s10;
                {
                    float e0 = __expf(sv0[0]); e0 = (W00.x >> bit) & 1 ? e0 : 0.0f;
                    float e1 = __expf(sv0[1]); e1 = (W00.y >> bit) & 1 ? e1 : 0.0f;
                    float e2 = __expf(sv0[2]); e2 = (W01.x >> bit) & 1 ? e2 : 0.0f;
                    float e3 = __expf(sv0[3]); e3 = (W01.y >> bit) & 1 ? e3 : 0.0f;
                    lr[0][0] += e0 + e1;
                    lr[0][1] += e2 + e3;
                    p[0][nf][0] = h2u(__floats2half2_rn(e0, e1));
                    p[0][nf][1] = h2u(__floats2half2_rn(e2, e3));
                }
                {
                    float e0 = __expf(sv1[0]); e0 = (W10.x >> bit) & 1 ? e0 : 0.0f;
                    float e1 = __expf(sv1[1]); e1 = (W10.y >> bit) & 1 ? e1 : 0.0f;
                    float e2 = __expf(sv1[2]); e2 = (W11.x >> bit) & 1 ? e2 : 0.0f;
                    float e3 = __expf(sv1[3]); e3 = (W11.y >> bit) & 1 ? e3 : 0.0f;
                    lr[1][0] += e0 + e1;
                    lr[1][1] += e2 + e3;
                    p[1][nf][0] = h2u(__floats2half2_rn(e0, e1));
                    p[1][nf][1] = h2u(__floats2half2_rn(e2, e3));
                }
            }
        }

#pragma unroll
        for (int kf = 0; kf < 4; kf++) {
            uint32_t ap0[4] = {p[0][2*kf][0], p[0][2*kf][1],
                               p[0][2*kf+1][0], p[0][2*kf+1][1]};
            uint32_t ap1[4] = {p[1][2*kf][0], p[1][2*kf][1],
                               p[1][2*kf+1][0], p[1][2*kf+1][1]};
#pragma unroll
            for (int nfp = 0; nfp < 4; nfp++) {
                uint32_t b0a, b1a, b0b, b1b;
                ldsm4(b0a, b1a, b0b, b1b,
                      &Vb[(nfp * 16 + br8) * AHS + kf * 16 + bhalf]);
                mma_f16(o[0][2*nfp],     ap0, b0a, b1a);
                mma_f16(o[0][2*nfp + 1], ap0, b0b, b1b);
                mma_f16(o[1][2*nfp],     ap1, b0a, b1a);
                mma_f16(o[1][2*nfp + 1], ap1, b0b, b1b);
            }
        }
    }

#pragma unroll
    for (int mi = 0; mi < 2; mi++) {
        lr[mi][0] += __shfl_xor_sync(0xffffffffu, lr[mi][0], 1);
        lr[mi][0] += __shfl_xor_sync(0xffffffffu, lr[mi][0], 2);
        lr[mi][1] += __shfl_xor_sync(0xffffffffu, lr[mi][1], 1);
        lr[mi][1] += __shfl_xor_sync(0xffffffffu, lr[mi][1], 2);
    }

#pragma unroll
    for (int mi = 0; mi < 2; mi++) {
        int rlo = wr + mi * 16 + g;
        float inv0 = 1.0f / lr[mi][0];
        float inv1 = 1.0f / lr[mi][1];
#pragma unroll
        for (int nf = 0; nf < 8; nf++) {
            int dh = h * DHH + nf*8 + 2*a;
            *(__half2*)&ctx[((size_t)(b * SS) + q0 + rlo) * DD + dh] =
                __floats2half2_rn(o[mi][nf][0] * inv0, o[mi][nf][1] * inv0);
            *(__half2*)&ctx[((size_t)(b * SS) + q0 + rlo + 8) * DD + dh] =
                __floats2half2_rn(o[mi][nf][2] * inv1, o[mi][nf][3] * inv1);
        }
    }
}

// ---------------------------------------------------------------------------
// Launch: mask_pack forked onto a second stream, overlapping cvt + QKV GEMM.
// ---------------------------------------------------------------------------
extern "C" void kernel_launch(void* const* d_in, const int* in_sizes, int n_in,
                              void* d_out, int out_size)
{
    const float* x   = (const float*)d_in[0];
    const float* y   = (const float*)d_in[1];
    const int*   msk = (const int*)  d_in[2];
    const float* Wq  = (const float*)d_in[3];
    const float* bq  = (const float*)d_in[4];
    const float* Wk  = (const float*)d_in[5];
    const float* bk  = (const float*)d_in[6];
    const float* Wv  = (const float*)d_in[7];
    const float* bv  = (const float*)d_in[8];
    const float* Wo  = (const float*)d_in[9];
    const float* bo  = (const float*)d_in[10];
    float* out = (float*)d_out;

    __half *Qg, *Kg, *Vg, *Cg, *xt, *yt, *wqt, *wkt, *wvt, *wot;
    uint2* mbg;
    cudaGetSymbolAddress((void**)&Qg,  g_Q);
    cudaGetSymbolAddress((void**)&Kg,  g_K);
    cudaGetSymbolAddress((void**)&Vg,  g_V);
    cudaGetSymbolAddress((void**)&Cg,  g_ctx);
    cudaGetSymbolAddress((void**)&xt,  g_xt);
    cudaGetSymbolAddress((void**)&yt,  g_yt);
    cudaGetSymbolAddress((void**)&wqt, g_Wqt);
    cudaGetSymbolAddress((void**)&wkt, g_Wkt);
    cudaGetSymbolAddress((void**)&wvt, g_Wvt);
    cudaGetSymbolAddress((void**)&wot, g_Wot);
    cudaGetSymbolAddress((void**)&mbg, g_mb);

    cudaFuncSetAttribute(gemm_f16_multi,
        cudaFuncAttributeMaxDynamicSharedMemorySize, GEMM_SMEM);
    cudaFuncSetAttribute(attn_f16,
        cudaFuncAttributeMaxDynamicSharedMemorySize, ATTN_SMEM);

    // One-time host objects (created on the uncaptured correctness call).
    static cudaStream_t s2 = nullptr;
    static cudaEvent_t evFork = nullptr, evJoin = nullptr;
    if (s2 == nullptr) {
        cudaStreamCreateWithFlags(&s2, cudaStreamNonBlocking);
        cudaEventCreateWithFlags(&evFork, cudaEventDisableTiming);
        cudaEventCreateWithFlags(&evJoin, cudaEventDisableTiming);
    }

    // Fork: mask_pack on s2 (depends only on input msk)
    cudaEventRecord(evFork, 0);
    cudaStreamWaitEvent(s2, evFork, 0);
    mask_pack_kernel<<<512, 256, 0, s2>>>(msk, mbg);
    cudaEventRecord(evJoin, s2);

    // Pre-pass: 6 cvt slots (default stream, concurrent with mask_pack)
    const int NX = BB * SS * DD / 4;
    const int NW = DD * DD / 4;
    PreArgs pa;
    pa.src[0] = x;  pa.dst[0] = xt;  pa.n4[0] = NX;
    pa.src[1] = y;  pa.dst[1] = yt;  pa.n4[1] = NX;
    pa.src[2] = Wq; pa.dst[2] = wqt; pa.n4[2] = NW;
    pa.src[3] = Wk; pa.dst[3] = wkt; pa.n4[3] = NW;
    pa.src[4] = Wv; pa.dst[4] = wvt; pa.n4[4] = NW;
    pa.src[5] = Wo; pa.dst[5] = wot; pa.n4[5] = NW;
    prepass_kernel<<<dim3(1024, 6), 256>>>(pa);

    // Fused Q + K + V^T projections: one launch, 768 CTAs
    GemmArgs ga;
    ga.sl[0] = {xt,  wqt, bq, (void*)Qg, 0.125f, 1};
    ga.sl[1] = {yt,  wkt, bk, (void*)Kg, 1.0f,   1};
    ga.sl[2] = {wvt, yt,  bv, (void*)Vg, 1.0f,   2};
    gemm_f16_multi<<<dim3(8, 32, 3), 256, GEMM_SMEM>>>(ga);

    // Join: attention needs the bitmask
    cudaStreamWaitEvent(0, evJoin, 0);
    attn_f16<<<dim3(SS / 128, HH, BB), 128, ATTN_SMEM>>>(Qg, Kg, Vg, mbg, Cg);

    // Output projection (single slice, mode 0)
    GemmArgs go;
    go.sl[0] = {Cg, wot, bo, (void*)out, 1.0f, 0};
    go.sl[1] = go.sl[0];
    go.sl[2] = go.sl[0];
    gemm_f16_multi<<<dim3(8, 32, 1), 256, GEMM_SMEM>>>(go);
}

// round 15
// speedup vs baseline: 1.0884x; 1.0782x over previous
#include <cuda_runtime.h>
#include <cuda_fp16.h>
#include <math.h>
#include <stdint.h>

// Problem constants
#define BB   2
#define SS   2048
#define DD   1024
#define HH   16
#define DHH  64

// Scratch (device globals; no allocation allowed)
__device__ __half g_Q  [BB*HH*SS*DHH];  // [B,H,S,DH], fp16, pre-scaled by 0.125
__device__ __half g_K  [BB*HH*SS*DHH];  // [B,H,S,DH]
__device__ __half g_V  [BB*DD*SS];      // TRANSPOSED: [B, dhn(=h*64+dh), S]
__device__ __half g_ctx[BB*SS*DD];      // [B,S,D]
__device__ __half g_xt [BB*SS*DD];
__device__ __half g_yt [BB*SS*DD];
__device__ __half g_Wqt[DD*DD];
__device__ __half g_Wkt[DD*DD];
__device__ __half g_Wvt[DD*DD];
__device__ __half g_Wot[DD*DD];
__device__ uint2  g_mb [BB*SS*(SS/64)]; // bitmask: [b][row][kv-tile64] {even,odd}

// ---------------------------------------------------------------------------
// Helpers
// ---------------------------------------------------------------------------
__device__ __forceinline__ void mma_f16(float d[4], const uint32_t a[4],
                                        uint32_t b0, uint32_t b1) {
    asm volatile(
        "mma.sync.aligned.m16n8k16.row.col.f32.f16.f16.f32 "
        "{%0,%1,%2,%3}, {%4,%5,%6,%7}, {%8,%9}, {%0,%1,%2,%3};"
        : "+f"(d[0]), "+f"(d[1]), "+f"(d[2]), "+f"(d[3])
        : "r"(a[0]), "r"(a[1]), "r"(a[2]), "r"(a[3]), "r"(b0), "r"(b1));
}

__device__ __forceinline__ void ldsm4(uint32_t& r0, uint32_t& r1,
                                      uint32_t& r2, uint32_t& r3,
                                      const __half* p) {
    uint32_t addr = (uint32_t)__cvta_generic_to_shared(p);
    asm volatile("ldmatrix.sync.aligned.m8n8.x4.shared.b16 {%0,%1,%2,%3}, [%4];"
                 : "=r"(r0), "=r"(r1), "=r"(r2), "=r"(r3) : "r"(addr));
}

__device__ __forceinline__ void cp16(void* smem_dst, const void* gsrc) {
    uint32_t s = (uint32_t)__cvta_generic_to_shared(smem_dst);
    asm volatile("cp.async.cg.shared.global [%0], [%1], 16;"
                 :: "r"(s), "l"(gsrc));
}
#define CP_COMMIT() asm volatile("cp.async.commit_group;")
#define CP_WAIT(n)  asm volatile("cp.async.wait_group %0;" :: "n"(n))

__device__ __forceinline__ uint32_t h2u(__half2 h) {
    return *(uint32_t*)&h;
}

// ---------------------------------------------------------------------------
// Fused pre-pass: fp32 -> fp16 (RN) for 6 tensors PLUS mask bitpack, one
// launch. grid.y in [0,5] = cvt slots; grid.y == 6 = mask pack.  (R12 form)
// ---------------------------------------------------------------------------
struct PreArgs {
    const float* src[6];
    __half*      dst[6];
    int          n4[6];
    const int*   mask;
    uint2*       mb;
};

__global__ void prepass_kernel(PreArgs args) {
    const int slot = blockIdx.y;
    if (slot < 6) {
        const float* __restrict__ src = args.src[slot];
        __half* __restrict__ dst = args.dst[slot];
        const int n4 = args.n4[slot];
        for (int i = blockIdx.x * blockDim.x + threadIdx.x; i < n4;
             i += gridDim.x * blockDim.x) {
            float4 v = ((const float4*)src)[i];
            __half2 h0 = __floats2half2_rn(v.x, v.y);
            __half2 h1 = __floats2half2_rn(v.z, v.w);
            uint2 u; u.x = h2u(h0); u.y = h2u(h1);
            ((uint2*)dst)[i] = u;
        }
    } else {
        const int lane = threadIdx.x & 31;
        const int warps_total = (gridDim.x * blockDim.x) >> 5;
        const int w0 = (blockIdx.x * blockDim.x + threadIdx.x) >> 5;
        const int n_tasks = BB * SS * (SS / 64);
        for (int t = w0; t < n_tasks; t += warps_total) {
            const size_t base = (size_t)t * 64;
            int v0 = args.mask[base + 2 * lane];
            int v1 = args.mask[base + 2 * lane + 1];
            uint32_t we = __ballot_sync(0xffffffffu, v0 != 0);
            uint32_t wo = __ballot_sync(0xffffffffu, v1 != 0);
            if (lane == 0) args.mb[t] = make_uint2(we, wo);
        }
    }
}

// ---------------------------------------------------------------------------
// fp16 GEMM, multi-slice (R12 form, unchanged).
// ---------------------------------------------------------------------------
#define GHS  72
#define GTILE (128 * GHS)
#define GEMM_SMEM (4 * GTILE * 2)   // 73728 B

struct GemmSlice {
    const __half* A;
    const __half* W;
    const float*  bias;
    void*         out;
    float         scale;
    int           mode;
};
struct GemmArgs { GemmSlice sl[3]; };

__global__ void __launch_bounds__(256, 2) gemm_f16_multi(GemmArgs args)
{
    extern __shared__ __half smh[];
    __half* As = smh;
    __half* Bs = smh + 2 * GTILE;

    const GemmSlice sl = args.sl[blockIdx.z];
    const int mode = sl.mode;
    const __half* __restrict__ A = sl.A;
    const __half* __restrict__ W = sl.W;
    const float*  __restrict__ bias = sl.bias;

    const int tid  = threadIdx.x;
    const int lane = tid & 31;
    const int wid  = tid >> 5;
    const int wm   = wid >> 2;
    const int wn   = wid & 3;
    const int g    = lane >> 2;
    const int a    = lane & 3;
    const int m0   = (mode == 2 ? blockIdx.x : blockIdx.y) * 128;
    const int n0   = (mode == 2 ? blockIdx.y : blockIdx.x) * 128;

    const int lr15  = lane & 15;
    const int ahalf = (lane >> 4) << 3;
    const int br8   = (lane & 7) + ((lane >> 4) << 3);
    const int bhalf = ((lane >> 3) & 1) << 3;

    float acc[4][4][4];
#pragma unroll
    for (int mi = 0; mi < 4; mi++)
#pragma unroll
        for (int nj = 0; nj < 4; nj++)
#pragma unroll
            for (int c = 0; c < 4; c++) acc[mi][nj][c] = 0.0f;

    auto stage = [&](int buf, int k0) {
#pragma unroll
        for (int i = 0; i < 4; i++) {
            int e = tid + 256 * i;
            int r = e >> 3, c8 = e & 7;
            cp16(&As[buf * GTILE + r * GHS + c8 * 8],
                 &A[(size_t)(m0 + r) * DD + k0 + c8 * 8]);
            cp16(&Bs[buf * GTILE + r * GHS + c8 * 8],
                 &W[(size_t)(n0 + r) * DD + k0 + c8 * 8]);
        }
    };

    stage(0, 0);
    CP_COMMIT();

    for (int s = 0; s < 16; s++) {
        if (s < 15) {
            stage((s + 1) & 1, (s + 1) * 64);
            CP_COMMIT();
            CP_WAIT(1);
        } else {
            CP_WAIT(0);
        }
        __syncthreads();

        const __half* Ab = &As[(s & 1) * GTILE];
        const __half* Bb = &Bs[(s & 1) * GTILE];

#pragma unroll
        for (int ks = 0; ks < 4; ks++) {
            uint32_t af[4][4], bf[4][2];
#pragma unroll
            for (int mi = 0; mi < 4; mi++)
                ldsm4(af[mi][0], af[mi][1], af[mi][2], af[mi][3],
                      &Ab[(wm * 64 + mi * 16 + lr15) * GHS + ks * 16 + ahalf]);
#pragma unroll
            for (int njp = 0; njp < 2; njp++)
                ldsm4(bf[2*njp][0], bf[2*njp][1], bf[2*njp+1][0], bf[2*njp+1][1],
                      &Bb[(wn * 32 + njp * 16 + br8) * GHS + ks * 16 + bhalf]);
#pragma unroll
            for (int mi = 0; mi < 4; mi++)
#pragma unroll
                for (int nj = 0; nj < 4; nj++)
                    mma_f16(acc[mi][nj], af[mi], bf[nj][0], bf[nj][1]);
        }
        __syncthreads();
    }

#pragma unroll
    for (int mi = 0; mi < 4; mi++) {
#pragma unroll
        for (int nj = 0; nj < 4; nj++) {
            int m = m0 + wm * 64 + mi * 16 + g;
            int n = n0 + wn * 32 + nj * 8 + 2 * a;
            if (mode == 2) {
                __half* out = (__half*)sl.out;
                float bm0 = bias[m], bm1 = bias[m + 8];
                int b = n >> 11, sq = n & 2047;
                size_t base = (size_t)b * DD * SS + sq;
                *(__half2*)&out[base + (size_t)m * SS] =
                    __floats2half2_rn(acc[mi][nj][0] + bm0, acc[mi][nj][1] + bm0);
                *(__half2*)&out[base + (size_t)(m + 8) * SS] =
                    __floats2half2_rn(acc[mi][nj][2] + bm1, acc[mi][nj][3] + bm1);
            } else if (mode == 1) {
                __half* out = (__half*)sl.out;
                float2 bv = *(const float2*)&bias[n];
                float scale = sl.scale;
                int h = n >> 6, dh = n & 63;
                int b1_ = m >> 11, s1 = m & 2047;
                *(__half2*)&out[(((size_t)(b1_ * HH + h)) * SS + s1) * DHH + dh] =
                    __floats2half2_rn((acc[mi][nj][0] + bv.x) * scale,
                                      (acc[mi][nj][1] + bv.y) * scale);
                int m2 = m + 8, b2_ = m2 >> 11, s2 = m2 & 2047;
                *(__half2*)&out[(((size_t)(b2_ * HH + h)) * SS + s2) * DHH + dh] =
                    __floats2half2_rn((acc[mi][nj][2] + bv.x) * scale,
                                      (acc[mi][nj][3] + bv.y) * scale);
            } else {
                float* out = (float*)sl.out;
                float2 bv = *(const float2*)&bias[n];
                *(float2*)&out[(size_t)m * DD + n] =
                    make_float2(acc[mi][nj][0] + bv.x, acc[mi][nj][1] + bv.y);
                *(float2*)&out[(size_t)(m + 8) * DD + n] =
                    make_float2(acc[mi][nj][2] + bv.x, acc[mi][nj][3] + bv.y);
            }
        }
    }
}

// ---------------------------------------------------------------------------
// Flash attention: S/PV interleaved (PV k-step nfp consumes the P fragments
// S-block nfp produces; identical fp32 accumulation order as the separated
// form -> bit-identical). p shrinks 32->8 regs; __launch_bounds__(128,3)
// caps regs at ~170 so 3 CTAs/SM (12 warps) fit. kv-tile 64, 3-deep ring.
// smem: K[3][64][72] + Vt[3][64][72] halves = 55296 B (3 CTAs = 166 KB).
// ---------------------------------------------------------------------------
#define AHS 72
#define AT  (64 * AHS)
#define ATTN_SMEM (6 * AT * 2)   // 55296 B

__global__ void __launch_bounds__(128, 3) attn_f16(
    const __half* __restrict__ Q, const __half* __restrict__ K,
    const __half* __restrict__ Vt, const uint2* __restrict__ mb,
    __half* __restrict__ ctx)
{
    extern __shared__ __half smh[];
    __half* Kr = smh;                 // [3][64][72]  rows=kv, cols=dh
    __half* Vr = smh + 3 * AT;        // [3][64][72]  rows=dh, cols=kv

    const int q0   = blockIdx.x * 128;
    const int h    = blockIdx.y;
    const int b    = blockIdx.z;
    const int tid  = threadIdx.x;
    const int lane = tid & 31;
    const int wid  = tid >> 5;
    const int g    = lane >> 2;
    const int a    = lane & 3;
    const int wr   = wid * 32;
    const int bh   = b * HH + h;

    const int br8   = (lane & 7) + ((lane >> 4) << 3);
    const int bhalf = ((lane >> 3) & 1) << 3;

    const __half* Qp  = Q  + ((size_t)bh * SS + q0) * DHH;
    const __half* Kp  = K  + (size_t)bh * SS * DHH;
    const __half* Vtp = Vt + ((size_t)b * DD + h * DHH) * SS;
    const uint2*  Mb  = mb + ((size_t)b * SS + q0) * (SS / 64);

    uint32_t aq[2][4][4];
#pragma unroll
    for (int mi = 0; mi < 2; mi++) {
        int r = wr + mi * 16 + g;
#pragma unroll
        for (int ks = 0; ks < 4; ks++) {
            aq[mi][ks][0] = *(const uint32_t*)&Qp[(r)     * DHH + ks*16 + 2*a];
            aq[mi][ks][1] = *(const uint32_t*)&Qp[(r + 8) * DHH + ks*16 + 2*a];
            aq[mi][ks][2] = *(const uint32_t*)&Qp[(r)     * DHH + ks*16 + 2*a + 8];
            aq[mi][ks][3] = *(const uint32_t*)&Qp[(r + 8) * DHH + ks*16 + 2*a + 8];
        }
    }

    float o[2][8][4];
#pragma unroll
    for (int mi = 0; mi < 2; mi++)
#pragma unroll
        for (int nf = 0; nf < 8; nf++)
#pragma unroll
            for (int c = 0; c < 4; c++) o[mi][nf][c] = 0.0f;
    float lr[2][2] = {{0.0f, 0.0f}, {0.0f, 0.0f}};

    auto stageKV = [&](int buf, int kv0) {
#pragma unroll
        for (int i = 0; i < 4; i++) {
            int e = tid + 128 * i;
            int r = e >> 3, c8 = e & 7;
            cp16(&Kr[buf * AT + r * AHS + c8 * 8],
                 &Kp[(size_t)(kv0 + r) * DHH + c8 * 8]);
            cp16(&Vr[buf * AT + r * AHS + c8 * 8],
                 &Vtp[(size_t)r * SS + kv0 + c8 * 8]);
        }
    };

    stageKV(0, 0);   CP_COMMIT();
    stageKV(1, 64);  CP_COMMIT();

    for (int it = 0; it < 32; it++) {
        const int kv0 = it * 64;
        const int buf = it % 3;
        if (it == 31) { CP_WAIT(0); } else { CP_WAIT(1); }
        __syncthreads();
        if (it + 2 < 32) {
            stageKV((it + 2) % 3, kv0 + 128);
            CP_COMMIT();
        }

        const __half* Kb = &Kr[buf * AT];
        const __half* Vb = &Vr[buf * AT];

        uint2 W00 = Mb[(size_t)(wr + g)      * (SS/64) + it];
        uint2 W01 = Mb[(size_t)(wr + 8 + g)  * (SS/64) + it];
        uint2 W10 = Mb[(size_t)(wr + 16 + g) * (SS/64) + it];
        uint2 W11 = Mb[(size_t)(wr + 24 + g) * (SS/64) + it];

        // Interleaved: S-block nfp -> exp/pack (8 regs) -> PV k-step kf = nfp
#pragma unroll
        for (int nfp = 0; nfp < 4; nfp++) {
            float s00[4] = {0,0,0,0}, s01[4] = {0,0,0,0};
            float s10[4] = {0,0,0,0}, s11[4] = {0,0,0,0};
#pragma unroll
            for (int ks = 0; ks < 4; ks++) {
                uint32_t b0a, b1a, b0b, b1b;
                ldsm4(b0a, b1a, b0b, b1b,
                      &Kb[(nfp * 16 + br8) * AHS + ks * 16 + bhalf]);
                mma_f16(s00, aq[0][ks], b0a, b1a);
                mma_f16(s01, aq[0][ks], b0b, b1b);
                mma_f16(s10, aq[1][ks], b0a, b1a);
                mma_f16(s11, aq[1][ks], b0b, b1b);
            }

            uint32_t ap0[4], ap1[4];
#pragma unroll
            for (int half_ = 0; half_ < 2; half_++) {
                int nf = nfp * 2 + half_;
                int bit = nf * 4 + a;
                const float* sv0 = half_ ? s01 : s00;
                const float* sv1 = half_ ? s11 : s10;
                {
                    float e0 = __expf(sv0[0]); e0 = (W00.x >> bit) & 1 ? e0 : 0.0f;
                    float e1 = __expf(sv0[1]); e1 = (W00.y >> bit) & 1 ? e1 : 0.0f;
                    float e2 = __expf(sv0[2]); e2 = (W01.x >> bit) & 1 ? e2 : 0.0f;
                    float e3 = __expf(sv0[3]); e3 = (W01.y >> bit) & 1 ? e3 : 0.0f;
                    lr[0][0] += e0 + e1;
                    lr[0][1] += e2 + e3;
                    ap0[2*half_]     = h2u(__floats2half2_rn(e0, e1));
                    ap0[2*half_ + 1] = h2u(__floats2half2_rn(e2, e3));
                }
                {
                    float e0 = __expf(sv1[0]); e0 = (W10.x >> bit) & 1 ? e0 : 0.0f;
                    float e1 = __expf(sv1[1]); e1 = (W10.y >> bit) & 1 ? e1 : 0.0f;
                    float e2 = __expf(sv1[2]); e2 = (W11.x >> bit) & 1 ? e2 : 0.0f;
                    float e3 = __expf(sv1[3]); e3 = (W11.y >> bit) & 1 ? e3 : 0.0f;
                    lr[1][0] += e0 + e1;
                    lr[1][1] += e2 + e3;
                    ap1[2*half_]     = h2u(__floats2half2_rn(e0, e1));
                    ap1[2*half_ + 1] = h2u(__floats2half2_rn(e2, e3));
                }
            }

            // PV k-step kf = nfp (same kf order 0..3 as separated form)
#pragma unroll
            for (int vf = 0; vf < 4; vf++) {
                uint32_t b0a, b1a, b0b, b1b;
                ldsm4(b0a, b1a, b0b, b1b,
                      &Vb[(vf * 16 + br8) * AHS + nfp * 16 + bhalf]);
                mma_f16(o[0][2*vf],     ap0, b0a, b1a);
                mma_f16(o[0][2*vf + 1], ap0, b0b, b1b);
                mma_f16(o[1][2*vf],     ap1, b0a, b1a);
                mma_f16(o[1][2*vf + 1], ap1, b0b, b1b);
            }
        }
    }

#pragma unroll
    for (int mi = 0; mi < 2; mi++) {
        lr[mi][0] += __shfl_xor_sync(0xffffffffu, lr[mi][0], 1);
        lr[mi][0] += __shfl_xor_sync(0xffffffffu, lr[mi][0], 2);
        lr[mi][1] += __shfl_xor_sync(0xffffffffu, lr[mi][1], 1);
        lr[mi][1] += __shfl_xor_sync(0xffffffffu, lr[mi][1], 2);
    }

#pragma unroll
    for (int mi = 0; mi < 2; mi++) {
        int rlo = wr + mi * 16 + g;
        float inv0 = 1.0f / lr[mi][0];
        float inv1 = 1.0f / lr[mi][1];
#pragma unroll
        for (int nf = 0; nf < 8; nf++) {
            int dh = h * DHH + nf*8 + 2*a;
            *(__half2*)&ctx[((size_t)(b * SS) + q0 + rlo) * DD + dh] =
                __floats2half2_rn(o[mi][nf][0] * inv0, o[mi][nf][1] * inv0);
            *(__half2*)&ctx[((size_t)(b * SS) + q0 + rlo + 8) * DD + dh] =
                __floats2half2_rn(o[mi][nf][2] * inv1, o[mi][nf][3] * inv1);
        }
    }
}

// ---------------------------------------------------------------------------
// Launch (R12 structure, single stream)
// ---------------------------------------------------------------------------
extern "C" void kernel_launch(void* const* d_in, const int* in_sizes, int n_in,
                              void* d_out, int out_size)
{
    const float* x   = (const float*)d_in[0];
    const float* y   = (const float*)d_in[1];
    const int*   msk = (const int*)  d_in[2];
    const float* Wq  = (const float*)d_in[3];
    const float* bq  = (const float*)d_in[4];
    const float* Wk  = (const float*)d_in[5];
    const float* bk  = (const float*)d_in[6];
    const float* Wv  = (const float*)d_in[7];
    const float* bv  = (const float*)d_in[8];
    const float* Wo  = (const float*)d_in[9];
    const float* bo  = (const float*)d_in[10];
    float* out = (float*)d_out;

    __half *Qg, *Kg, *Vg, *Cg, *xt, *yt, *wqt, *wkt, *wvt, *wot;
    uint2* mbg;
    cudaGetSymbolAddress((void**)&Qg,  g_Q);
    cudaGetSymbolAddress((void**)&Kg,  g_K);
    cudaGetSymbolAddress((void**)&Vg,  g_V);
    cudaGetSymbolAddress((void**)&Cg,  g_ctx);
    cudaGetSymbolAddress((void**)&xt,  g_xt);
    cudaGetSymbolAddress((void**)&yt,  g_yt);
    cudaGetSymbolAddress((void**)&wqt, g_Wqt);
    cudaGetSymbolAddress((void**)&wkt, g_Wkt);
    cudaGetSymbolAddress((void**)&wvt, g_Wvt);
    cudaGetSymbolAddress((void**)&wot, g_Wot);
    cudaGetSymbolAddress((void**)&mbg, g_mb);

    cudaFuncSetAttribute(gemm_f16_multi,
        cudaFuncAttributeMaxDynamicSharedMemorySize, GEMM_SMEM);
    cudaFuncSetAttribute(attn_f16,
        cudaFuncAttributeMaxDynamicSharedMemorySize, ATTN_SMEM);

    // Single merged pre-pass: 6 cvt slots + mask bitpack (grid.y = 7)
    const int NX = BB * SS * DD / 4;
    const int NW = DD * DD / 4;
    PreArgs pa;
    pa.src[0] = x;  pa.dst[0] = xt;  pa.n4[0] = NX;
    pa.src[1] = y;  pa.dst[1] = yt;  pa.n4[1] = NX;
    pa.src[2] = Wq; pa.dst[2] = wqt; pa.n4[2] = NW;
    pa.src[3] = Wk; pa.dst[3] = wkt; pa.n4[3] = NW;
    pa.src[4] = Wv; pa.dst[4] = wvt; pa.n4[4] = NW;
    pa.src[5] = Wo; pa.dst[5] = wot; pa.n4[5] = NW;
    pa.mask = msk;
    pa.mb   = mbg;
    prepass_kernel<<<dim3(1024, 7), 256>>>(pa);

    // Fused Q + K + V^T projections: one launch, 768 CTAs
    GemmArgs ga;
    ga.sl[0] = {xt,  wqt, bq, (void*)Qg, 0.125f, 1};
    ga.sl[1] = {yt,  wkt, bk, (void*)Kg, 1.0f,   1};
    ga.sl[2] = {wvt, yt,  bv, (void*)Vg, 1.0f,   2};
    gemm_f16_multi<<<dim3(8, 32, 3), 256, GEMM_SMEM>>>(ga);

    attn_f16<<<dim3(SS / 128, HH, BB), 128, ATTN_SMEM>>>(Qg, Kg, Vg, mbg, Cg);

    // Output projection (single slice, mode 0)
    GemmArgs go;
    go.sl[0] = {Cg, wot, bo, (void*)out, 1.0f, 0};
    go.sl[1] = go.sl[0];
    go.sl[2] = go.sl[0];
    gemm_f16_multi<<<dim3(8, 32, 1), 256, GEMM_SMEM>>>(go);
}

// round 16
// speedup vs baseline: 1.1590x; 1.0648x over previous
#include <cuda_runtime.h>
#include <cuda_fp16.h>
#include <math.h>
#include <stdint.h>

// Problem constants
#define BB   2
#define SS   2048
#define DD   1024
#define HH   16
#define DHH  64

// Scratch (device globals; no allocation allowed)
__device__ __half g_Q  [BB*HH*SS*DHH];  // [B,H,S,DH], fp16, pre-scaled by 0.125
__device__ __half g_K  [BB*HH*SS*DHH];  // [B,H,S,DH]
__device__ __half g_V  [BB*DD*SS];      // TRANSPOSED: [B, dhn(=h*64+dh), S]
__device__ __half g_ctx[BB*SS*DD];      // [B,S,D]
__device__ __half g_xt [BB*SS*DD];
__device__ __half g_yt [BB*SS*DD];
__device__ __half g_Wqt[DD*DD];
__device__ __half g_Wkt[DD*DD];
__device__ __half g_Wvt[DD*DD];
__device__ __half g_Wot[DD*DD];
__device__ uint2  g_mb [BB*SS*(SS/64)]; // bitmask: [b][row][kv-tile64] {even,odd}

// ---------------------------------------------------------------------------
// Helpers
// ---------------------------------------------------------------------------
__device__ __forceinline__ void mma_f16(float d[4], const uint32_t a[4],
                                        uint32_t b0, uint32_t b1) {
    asm volatile(
        "mma.sync.aligned.m16n8k16.row.col.f32.f16.f16.f32 "
        "{%0,%1,%2,%3}, {%4,%5,%6,%7}, {%8,%9}, {%0,%1,%2,%3};"
        : "+f"(d[0]), "+f"(d[1]), "+f"(d[2]), "+f"(d[3])
        : "r"(a[0]), "r"(a[1]), "r"(a[2]), "r"(a[3]), "r"(b0), "r"(b1));
}

__device__ __forceinline__ void ldsm4(uint32_t& r0, uint32_t& r1,
                                      uint32_t& r2, uint32_t& r3,
                                      const __half* p) {
    uint32_t addr = (uint32_t)__cvta_generic_to_shared(p);
    asm volatile("ldmatrix.sync.aligned.m8n8.x4.shared.b16 {%0,%1,%2,%3}, [%4];"
                 : "=r"(r0), "=r"(r1), "=r"(r2), "=r"(r3) : "r"(addr));
}

__device__ __forceinline__ void cp16(void* smem_dst, const void* gsrc) {
    uint32_t s = (uint32_t)__cvta_generic_to_shared(smem_dst);
    asm volatile("cp.async.cg.shared.global [%0], [%1], 16;"
                 :: "r"(s), "l"(gsrc));
}
#define CP_COMMIT() asm volatile("cp.async.commit_group;")
#define CP_WAIT(n)  asm volatile("cp.async.wait_group %0;" :: "n"(n))

__device__ __forceinline__ uint32_t h2u(__half2 h) {
    return *(uint32_t*)&h;
}

// ---------------------------------------------------------------------------
// Fused pre-pass: fp32 -> fp16 (RN) for 6 tensors PLUS mask bitpack, one
// launch. grid.y in [0,5] = cvt slots; grid.y == 6 = mask pack.
// ---------------------------------------------------------------------------
struct PreArgs {
    const float* src[6];
    __half*      dst[6];
    int          n4[6];
    const int*   mask;
    uint2*       mb;
};

__global__ void prepass_kernel(PreArgs args) {
    const int slot = blockIdx.y;
    if (slot < 6) {
        const float* __restrict__ src = args.src[slot];
        __half* __restrict__ dst = args.dst[slot];
        const int n4 = args.n4[slot];
        for (int i = blockIdx.x * blockDim.x + threadIdx.x; i < n4;
             i += gridDim.x * blockDim.x) {
            float4 v = ((const float4*)src)[i];
            __half2 h0 = __floats2half2_rn(v.x, v.y);
            __half2 h1 = __floats2half2_rn(v.z, v.w);
            uint2 u; u.x = h2u(h0); u.y = h2u(h1);
            ((uint2*)dst)[i] = u;
        }
    } else {
        const int lane = threadIdx.x & 31;
        const int warps_total = (gridDim.x * blockDim.x) >> 5;
        const int w0 = (blockIdx.x * blockDim.x + threadIdx.x) >> 5;
        const int n_tasks = BB * SS * (SS / 64);
        for (int t = w0; t < n_tasks; t += warps_total) {
            const size_t base = (size_t)t * 64;
            int v0 = args.mask[base + 2 * lane];
            int v1 = args.mask[base + 2 * lane + 1];
            uint32_t we = __ballot_sync(0xffffffffu, v0 != 0);
            uint32_t wo = __ballot_sync(0xffffffffu, v1 != 0);
            if (lane == 0) args.mb[t] = make_uint2(we, wo);
        }
    }
}

// ---------------------------------------------------------------------------
// fp16 GEMM, multi-slice (unchanged from R12/R15).
// ---------------------------------------------------------------------------
#define GHS  72
#define GTILE (128 * GHS)
#define GEMM_SMEM (4 * GTILE * 2)   // 73728 B

struct GemmSlice {
    const __half* A;
    const __half* W;
    const float*  bias;
    void*         out;
    float         scale;
    int           mode;
};
struct GemmArgs { GemmSlice sl[3]; };

__global__ void __launch_bounds__(256, 2) gemm_f16_multi(GemmArgs args)
{
    extern __shared__ __half smh[];
    __half* As = smh;
    __half* Bs = smh + 2 * GTILE;

    const GemmSlice sl = args.sl[blockIdx.z];
    const int mode = sl.mode;
    const __half* __restrict__ A = sl.A;
    const __half* __restrict__ W = sl.W;
    const float*  __restrict__ bias = sl.bias;

    const int tid  = threadIdx.x;
    const int lane = tid & 31;
    const int wid  = tid >> 5;
    const int wm   = wid >> 2;
    const int wn   = wid & 3;
    const int g    = lane >> 2;
    const int a    = lane & 3;
    const int m0   = (mode == 2 ? blockIdx.x : blockIdx.y) * 128;
    const int n0   = (mode == 2 ? blockIdx.y : blockIdx.x) * 128;

    const int lr15  = lane & 15;
    const int ahalf = (lane >> 4) << 3;
    const int br8   = (lane & 7) + ((lane >> 4) << 3);
    const int bhalf = ((lane >> 3) & 1) << 3;

    float acc[4][4][4];
#pragma unroll
    for (int mi = 0; mi < 4; mi++)
#pragma unroll
        for (int nj = 0; nj < 4; nj++)
#pragma unroll
            for (int c = 0; c < 4; c++) acc[mi][nj][c] = 0.0f;

    auto stage = [&](int buf, int k0) {
#pragma unroll
        for (int i = 0; i < 4; i++) {
            int e = tid + 256 * i;
            int r = e >> 3, c8 = e & 7;
            cp16(&As[buf * GTILE + r * GHS + c8 * 8],
                 &A[(size_t)(m0 + r) * DD + k0 + c8 * 8]);
            cp16(&Bs[buf * GTILE + r * GHS + c8 * 8],
                 &W[(size_t)(n0 + r) * DD + k0 + c8 * 8]);
        }
    };

    stage(0, 0);
    CP_COMMIT();

    for (int s = 0; s < 16; s++) {
        if (s < 15) {
            stage((s + 1) & 1, (s + 1) * 64);
            CP_COMMIT();
            CP_WAIT(1);
        } else {
            CP_WAIT(0);
        }
        __syncthreads();

        const __half* Ab = &As[(s & 1) * GTILE];
        const __half* Bb = &Bs[(s & 1) * GTILE];

#pragma unroll
        for (int ks = 0; ks < 4; ks++) {
            uint32_t af[4][4], bf[4][2];
#pragma unroll
            for (int mi = 0; mi < 4; mi++)
                ldsm4(af[mi][0], af[mi][1], af[mi][2], af[mi][3],
                      &Ab[(wm * 64 + mi * 16 + lr15) * GHS + ks * 16 + ahalf]);
#pragma unroll
            for (int njp = 0; njp < 2; njp++)
                ldsm4(bf[2*njp][0], bf[2*njp][1], bf[2*njp+1][0], bf[2*njp+1][1],
                      &Bb[(wn * 32 + njp * 16 + br8) * GHS + ks * 16 + bhalf]);
#pragma unroll
            for (int mi = 0; mi < 4; mi++)
#pragma unroll
                for (int nj = 0; nj < 4; nj++)
                    mma_f16(acc[mi][nj], af[mi], bf[nj][0], bf[nj][1]);
        }
        __syncthreads();
    }

#pragma unroll
    for (int mi = 0; mi < 4; mi++) {
#pragma unroll
        for (int nj = 0; nj < 4; nj++) {
            int m = m0 + wm * 64 + mi * 16 + g;
            int n = n0 + wn * 32 + nj * 8 + 2 * a;
            if (mode == 2) {
                __half* out = (__half*)sl.out;
                float bm0 = bias[m], bm1 = bias[m + 8];
                int b = n >> 11, sq = n & 2047;
                size_t base = (size_t)b * DD * SS + sq;
                *(__half2*)&out[base + (size_t)m * SS] =
                    __floats2half2_rn(acc[mi][nj][0] + bm0, acc[mi][nj][1] + bm0);
                *(__half2*)&out[base + (size_t)(m + 8) * SS] =
                    __floats2half2_rn(acc[mi][nj][2] + bm1, acc[mi][nj][3] + bm1);
            } else if (mode == 1) {
                __half* out = (__half*)sl.out;
                float2 bv = *(const float2*)&bias[n];
                float scale = sl.scale;
                int h = n >> 6, dh = n & 63;
                int b1_ = m >> 11, s1 = m & 2047;
                *(__half2*)&out[(((size_t)(b1_ * HH + h)) * SS + s1) * DHH + dh] =
                    __floats2half2_rn((acc[mi][nj][0] + bv.x) * scale,
                                      (acc[mi][nj][1] + bv.y) * scale);
                int m2 = m + 8, b2_ = m2 >> 11, s2 = m2 & 2047;
                *(__half2*)&out[(((size_t)(b2_ * HH + h)) * SS + s2) * DHH + dh] =
                    __floats2half2_rn((acc[mi][nj][2] + bv.x) * scale,
                                      (acc[mi][nj][3] + bv.y) * scale);
            } else {
                float* out = (float*)sl.out;
                float2 bv = *(const float2*)&bias[n];
                *(float2*)&out[(size_t)m * DD + n] =
                    make_float2(acc[mi][nj][0] + bv.x, acc[mi][nj][1] + bv.y);
                *(float2*)&out[(size_t)(m + 8) * DD + n] =
                    make_float2(acc[mi][nj][2] + bv.x, acc[mi][nj][3] + bv.y);
            }
        }
    }
}

// ---------------------------------------------------------------------------
// Flash attention: q-tile 64 (4 warps, 16 rows/warp, mi=1) for wave fill:
// grid 1024 CTAs on 592 slots (4 CTAs/SM) = 86% fill vs 58% at q-tile 128.
// Interleaved S(nfp)->exp->PV(kf=nfp), P in 4 regs, bitmask, kv-64 3-ring.
// Per-row compute order identical to R15 -> bit-identical output.
// smem: K[3][64][72] + Vt[3][64][72] halves = 55296 B (4 CTAs = 221 KB).
// ---------------------------------------------------------------------------
#define AHS 72
#define AT  (64 * AHS)
#define ATTN_SMEM (6 * AT * 2)   // 55296 B

__global__ void __launch_bounds__(128, 4) attn_f16(
    const __half* __restrict__ Q, const __half* __restrict__ K,
    const __half* __restrict__ Vt, const uint2* __restrict__ mb,
    __half* __restrict__ ctx)
{
    extern __shared__ __half smh[];
    __half* Kr = smh;                 // [3][64][72]  rows=kv, cols=dh
    __half* Vr = smh + 3 * AT;        // [3][64][72]  rows=dh, cols=kv

    const int q0   = blockIdx.x * 64;
    const int h    = blockIdx.y;
    const int b    = blockIdx.z;
    const int tid  = threadIdx.x;
    const int lane = tid & 31;
    const int wid  = tid >> 5;
    const int g    = lane >> 2;
    const int a    = lane & 3;
    const int wr   = wid * 16;          // 16 q-rows per warp
    const int bh   = b * HH + h;

    const int br8   = (lane & 7) + ((lane >> 4) << 3);
    const int bhalf = ((lane >> 3) & 1) << 3;

    const __half* Qp  = Q  + ((size_t)bh * SS + q0) * DHH;
    const __half* Kp  = K  + (size_t)bh * SS * DHH;
    const __half* Vtp = Vt + ((size_t)b * DD + h * DHH) * SS;
    const uint2*  Mb  = mb + ((size_t)b * SS + q0) * (SS / 64);

    // Q fragments resident: 4 k16-steps (rows wr+g, wr+8+g)
    uint32_t aq[4][4];
#pragma unroll
    for (int ks = 0; ks < 4; ks++) {
        aq[ks][0] = *(const uint32_t*)&Qp[(wr + g)     * DHH + ks*16 + 2*a];
        aq[ks][1] = *(const uint32_t*)&Qp[(wr + 8 + g) * DHH + ks*16 + 2*a];
        aq[ks][2] = *(const uint32_t*)&Qp[(wr + g)     * DHH + ks*16 + 2*a + 8];
        aq[ks][3] = *(const uint32_t*)&Qp[(wr + 8 + g) * DHH + ks*16 + 2*a + 8];
    }

    float o[8][4];
#pragma unroll
    for (int nf = 0; nf < 8; nf++)
#pragma unroll
        for (int c = 0; c < 4; c++) o[nf][c] = 0.0f;
    float lr0 = 0.0f, lr1 = 0.0f;

    auto stageKV = [&](int buf, int kv0) {
#pragma unroll
        for (int i = 0; i < 4; i++) {
            int e = tid + 128 * i;
            int r = e >> 3, c8 = e & 7;
            cp16(&Kr[buf * AT + r * AHS + c8 * 8],
                 &Kp[(size_t)(kv0 + r) * DHH + c8 * 8]);
            cp16(&Vr[buf * AT + r * AHS + c8 * 8],
                 &Vtp[(size_t)r * SS + kv0 + c8 * 8]);
        }
    };

    stageKV(0, 0);   CP_COMMIT();
    stageKV(1, 64);  CP_COMMIT();

    for (int it = 0; it < 32; it++) {
        const int kv0 = it * 64;
        const int buf = it % 3;
        if (it == 31) { CP_WAIT(0); } else { CP_WAIT(1); }
        __syncthreads();
        if (it + 2 < 32) {
            stageKV((it + 2) % 3, kv0 + 128);
            CP_COMMIT();
        }

        const __half* Kb = &Kr[buf * AT];
        const __half* Vb = &Vr[buf * AT];

        uint2 W00 = Mb[(size_t)(wr + g)     * (SS/64) + it];
        uint2 W01 = Mb[(size_t)(wr + 8 + g) * (SS/64) + it];

        // Interleaved: S-block nfp -> exp/pack (4 regs) -> PV k-step kf = nfp
#pragma unroll
        for (int nfp = 0; nfp < 4; nfp++) {
            float s0[4] = {0,0,0,0}, s1[4] = {0,0,0,0};
#pragma unroll
            for (int ks = 0; ks < 4; ks++) {
                uint32_t b0a, b1a, b0b, b1b;
                ldsm4(b0a, b1a, b0b, b1b,
                      &Kb[(nfp * 16 + br8) * AHS + ks * 16 + bhalf]);
                mma_f16(s0, aq[ks], b0a, b1a);
                mma_f16(s1, aq[ks], b0b, b1b);
            }

            uint32_t ap[4];
#pragma unroll
            for (int half_ = 0; half_ < 2; half_++) {
                int nf = nfp * 2 + half_;
                int bit = nf * 4 + a;
                const float* sv = half_ ? s1 : s0;
                float e0 = __expf(sv[0]); e0 = (W00.x >> bit) & 1 ? e0 : 0.0f;
                float e1 = __expf(sv[1]); e1 = (W00.y >> bit) & 1 ? e1 : 0.0f;
                float e2 = __expf(sv[2]); e2 = (W01.x >> bit) & 1 ? e2 : 0.0f;
                float e3 = __expf(sv[3]); e3 = (W01.y >> bit) & 1 ? e3 : 0.0f;
                lr0 += e0 + e1;
                lr1 += e2 + e3;
                ap[2*half_]     = h2u(__floats2half2_rn(e0, e1));
                ap[2*half_ + 1] = h2u(__floats2half2_rn(e2, e3));
            }

            // PV k-step kf = nfp
#pragma unroll
            for (int vf = 0; vf < 4; vf++) {
                uint32_t b0a, b1a, b0b, b1b;
                ldsm4(b0a, b1a, b0b, b1b,
                      &Vb[(vf * 16 + br8) * AHS + nfp * 16 + bhalf]);
                mma_f16(o[2*vf],     ap, b0a, b1a);
                mma_f16(o[2*vf + 1], ap, b0b, b1b);
            }
        }
    }

    // Final l reduction across the quad, then epilogue (ctx as fp16)
    lr0 += __shfl_xor_sync(0xffffffffu, lr0, 1);
    lr0 += __shfl_xor_sync(0xffffffffu, lr0, 2);
    lr1 += __shfl_xor_sync(0xffffffffu, lr1, 1);
    lr1 += __shfl_xor_sync(0xffffffffu, lr1, 2);

    const int rlo = wr + g;
    float inv0 = 1.0f / lr0;
    float inv1 = 1.0f / lr1;
#pragma unroll
    for (int nf = 0; nf < 8; nf++) {
        int dh = h * DHH + nf*8 + 2*a;
        *(__half2*)&ctx[((size_t)(b * SS) + q0 + rlo) * DD + dh] =
            __floats2half2_rn(o[nf][0] * inv0, o[nf][1] * inv0);
        *(__half2*)&ctx[((size_t)(b * SS) + q0 + rlo + 8) * DD + dh] =
            __floats2half2_rn(o[nf][2] * inv1, o[nf][3] * inv1);
    }
}

// ---------------------------------------------------------------------------
// Launch
// ---------------------------------------------------------------------------
extern "C" void kernel_launch(void* const* d_in, const int* in_sizes, int n_in,
                              void* d_out, int out_size)
{
    const float* x   = (const float*)d_in[0];
    const float* y   = (const float*)d_in[1];
    const int*   msk = (const int*)  d_in[2];
    const float* Wq  = (const float*)d_in[3];
    const float* bq  = (const float*)d_in[4];
    const float* Wk  = (const float*)d_in[5];
    const float* bk  = (const float*)d_in[6];
    const float* Wv  = (const float*)d_in[7];
    const float* bv  = (const float*)d_in[8];
    const float* Wo  = (const float*)d_in[9];
    const float* bo  = (const float*)d_in[10];
    float* out = (float*)d_out;

    __half *Qg, *Kg, *Vg, *Cg, *xt, *yt, *wqt, *wkt, *wvt, *wot;
    uint2* mbg;
    cudaGetSymbolAddress((void**)&Qg,  g_Q);
    cudaGetSymbolAddress((void**)&Kg,  g_K);
    cudaGetSymbolAddress((void**)&Vg,  g_V);
    cudaGetSymbolAddress((void**)&Cg,  g_ctx);
    cudaGetSymbolAddress((void**)&xt,  g_xt);
    cudaGetSymbolAddress((void**)&yt,  g_yt);
    cudaGetSymbolAddress((void**)&wqt, g_Wqt);
    cudaGetSymbolAddress((void**)&wkt, g_Wkt);
    cudaGetSymbolAddress((void**)&wvt, g_Wvt);
    cudaGetSymbolAddress((void**)&wot, g_Wot);
    cudaGetSymbolAddress((void**)&mbg, g_mb);

    cudaFuncSetAttribute(gemm_f16_multi,
        cudaFuncAttributeMaxDynamicSharedMemorySize, GEMM_SMEM);
    cudaFuncSetAttribute(attn_f16,
        cudaFuncAttributeMaxDynamicSharedMemorySize, ATTN_SMEM);

    // Single merged pre-pass: 6 cvt slots + mask bitpack (grid.y = 7)
    const int NX = BB * SS * DD / 4;
    const int NW = DD * DD / 4;
    PreArgs pa;
    pa.src[0] = x;  pa.dst[0] = xt;  pa.n4[0] = NX;
    pa.src[1] = y;  pa.dst[1] = yt;  pa.n4[1] = NX;
    pa.src[2] = Wq; pa.dst[2] = wqt; pa.n4[2] = NW;
    pa.src[3] = Wk; pa.dst[3] = wkt; pa.n4[3] = NW;
    pa.src[4] = Wv; pa.dst[4] = wvt; pa.n4[4] = NW;
    pa.src[5] = Wo; pa.dst[5] = wot; pa.n4[5] = NW;
    pa.mask = msk;
    pa.mb   = mbg;
    prepass_kernel<<<dim3(1024, 7), 256>>>(pa);

    // Fused Q + K + V^T projections: one launch, 768 CTAs
    GemmArgs ga;
    ga.sl[0] = {xt,  wqt, bq, (void*)Qg, 0.125f, 1};
    ga.sl[1] = {yt,  wkt, bk, (void*)Kg, 1.0f,   1};
    ga.sl[2] = {wvt, yt,  bv, (void*)Vg, 1.0f,   2};
    gemm_f16_multi<<<dim3(8, 32, 3), 256, GEMM_SMEM>>>(ga);

    // Attention: q-tile 64 -> 1024 CTAs, 4 CTAs/SM (86% slot fill)
    attn_f16<<<dim3(SS / 64, HH, BB), 128, ATTN_SMEM>>>(Qg, Kg, Vg, mbg, Cg);

    // Output projection (single slice, mode 0)
    GemmArgs go;
    go.sl[0] = {Cg, wot, bo, (void*)out, 1.0f, 0};
    go.sl[1] = go.sl[0];
    go.sl[2] = go.sl[0];
    gemm_f16_multi<<<dim3(8, 32, 1), 256, GEMM_SMEM>>>(go);
}